// round 7
// baseline (speedup 1.0000x reference)
#include <cuda_runtime.h>
#include <cuda_bf16.h>
#include <math.h>
#include <stdint.h>

// Shapes fixed by dataset: x[8,2048,1024] f32, Wg[1024,8], W1[8,1024,2048],
// W2[8,2048,1024]. T = 16384 tokens, top-2 of 8 experts.
#define HDIM 1024
#define FDIM 2048
#define NE   8
#define MAXT 16384

// ------------------- device-global scratch ------------------------------
__device__ int   g_ecnt[NE];
__device__ int   g_off[NE + 1];
__device__ int   g_etok[NE * MAXT];
__device__ float g_ecw [NE * MAXT];
__device__ float g_zacc;
__device__ int   g_cnt0, g_cnt1;
__device__ float g_sumw0, g_sumw1;
// bf16 hi/lo splits. Weights stored TRANSPOSED: w1t [e][F][H], w2t [e][H][F]
__device__ __nv_bfloat16 g_xh[(size_t)MAXT * HDIM];
__device__ __nv_bfloat16 g_xl[(size_t)MAXT * HDIM];
__device__ __nv_bfloat16 g_w1h[(size_t)NE * HDIM * FDIM];
__device__ __nv_bfloat16 g_w1l[(size_t)NE * HDIM * FDIM];
__device__ __nv_bfloat16 g_w2h[(size_t)NE * FDIM * HDIM];
__device__ __nv_bfloat16 g_w2l[(size_t)NE * FDIM * HDIM];
// hidden activations (compacted rows), hi/lo, K-contiguous [2T][F]
__device__ __nv_bfloat16 g_hh[(size_t)2 * MAXT * FDIM];
__device__ __nv_bfloat16 g_hl[(size_t)2 * MAXT * FDIM];

// ------------------- helpers --------------------------------------------
__device__ __forceinline__ uint32_t smem_u32(const void* p) {
    uint32_t a;
    asm("{ .reg .u64 t; cvta.to.shared.u64 t, %1; cvt.u32.u64 %0, t; }"
        : "=r"(a) : "l"(p));
    return a;
}
__device__ __forceinline__ void cpa16(uint32_t dst, const void* src, bool valid) {
    int sz = valid ? 16 : 0;
    asm volatile("cp.async.cg.shared.global [%0], [%1], 16, %2;"
                 :: "r"(dst), "l"(src), "r"(sz) : "memory");
}
__device__ __forceinline__ void cpa_commit() {
    asm volatile("cp.async.commit_group;" ::: "memory");
}
__device__ __forceinline__ void mma_bf16(float* c, const uint32_t* a, const uint32_t* b) {
    asm volatile(
        "mma.sync.aligned.m16n8k16.row.col.f32.bf16.bf16.f32 "
        "{%0,%1,%2,%3}, {%4,%5,%6,%7}, {%8,%9}, {%0,%1,%2,%3};"
        : "+f"(c[0]), "+f"(c[1]), "+f"(c[2]), "+f"(c[3])
        : "r"(a[0]), "r"(a[1]), "r"(a[2]), "r"(a[3]), "r"(b[0]), "r"(b[1]));
}
__device__ __forceinline__ void ldsm4(uint32_t addr, uint32_t* r) {
    asm volatile("ldmatrix.sync.aligned.m8n8.x4.shared.b16 {%0,%1,%2,%3}, [%4];"
                 : "=r"(r[0]), "=r"(r[1]), "=r"(r[2]), "=r"(r[3]) : "r"(addr));
}

// SMEM tile geometry: K-tile 32, rows padded to 80 B (64 B payload + 16 pad;
// 20r mod 32 banks distinct per 8-lane ldmatrix phase -> conflict-free).
#define ROWB 80
#define A_LO   5120          // 64 rows * 80
#define B_HI  10240
#define B_LO  30720          // B_HI + 256*80
#define STAGEB 51200
#define NSTAGE 2
#define SMEM_BYTES (NSTAGE * STAGEB)   // 102400

// ------------------- zero / reset ---------------------------------------
__global__ void zero_kernel(float* __restrict__ out, long long n) {
    long long i = (long long)blockIdx.x * blockDim.x + threadIdx.x;
    long long stride = (long long)gridDim.x * blockDim.x;
    for (; i < n; i += stride) out[i] = 0.0f;
    if (blockIdx.x == 0) {
        if (threadIdx.x == 0) {
            g_zacc = 0.0f; g_cnt0 = 0; g_cnt1 = 0;
            g_sumw0 = 0.0f; g_sumw1 = 0.0f;
        }
        if (threadIdx.x < NE) g_ecnt[threadIdx.x] = 0;
    }
}

// ------------------- router ---------------------------------------------
__global__ void router_kernel(const float* __restrict__ x,
                              const float* __restrict__ Wg, int T) {
    int warp = (blockIdx.x * blockDim.x + threadIdx.x) >> 5;
    int lane = threadIdx.x & 31;
    if (warp >= T) return;
    const float* xr = x + (size_t)warp * HDIM;

    float acc[NE];
#pragma unroll
    for (int e = 0; e < NE; ++e) acc[e] = 0.0f;
    for (int i = lane; i < HDIM; i += 32) {
        float xv = xr[i];
        float4 w0 = *(const float4*)(Wg + (size_t)i * NE);
        float4 w1 = *(const float4*)(Wg + (size_t)i * NE + 4);
        acc[0] += xv * w0.x; acc[1] += xv * w0.y;
        acc[2] += xv * w0.z; acc[3] += xv * w0.w;
        acc[4] += xv * w1.x; acc[5] += xv * w1.y;
        acc[6] += xv * w1.z; acc[7] += xv * w1.w;
    }
#pragma unroll
    for (int off = 16; off > 0; off >>= 1)
#pragma unroll
        for (int e = 0; e < NE; ++e)
            acc[e] += __shfl_xor_sync(0xFFFFFFFFu, acc[e], off);

    if (lane == 0) {
        float m = acc[0];
#pragma unroll
        for (int e = 1; e < NE; ++e) m = fmaxf(m, acc[e]);
        float p[NE], s = 0.0f;
#pragma unroll
        for (int e = 0; e < NE; ++e) { p[e] = __expf(acc[e] - m); s += p[e]; }
        float lse = m + logf(s);
        atomicAdd(&g_zacc, lse * lse);

        int i0 = 0;
#pragma unroll
        for (int e = 1; e < NE; ++e) if (p[e] > p[i0]) i0 = e;
        int i1 = (i0 == 0) ? 1 : 0;
#pragma unroll
        for (int e = 0; e < NE; ++e) if (e != i0 && p[e] > p[i1]) i1 = e;
        float w0 = p[i0] / s, w1 = p[i1] / s;

        atomicAdd(&g_sumw0, w0);
        atomicAdd(&g_sumw1, w1);
        if (i0 == 0 || i1 == 0) atomicAdd(&g_cnt0, 1);
        if (i0 == 1 || i1 == 1) atomicAdd(&g_cnt1, 1);

        int p0 = atomicAdd(&g_ecnt[i0], 1);
        g_etok[i0 * MAXT + p0] = warp; g_ecw[i0 * MAXT + p0] = w0;
        int p1 = atomicAdd(&g_ecnt[i1], 1);
        g_etok[i1 * MAXT + p1] = warp; g_ecw[i1 * MAXT + p1] = w1;
    }
}

__global__ void scan_kernel() {
    if (threadIdx.x == 0) {
        int s = 0; g_off[0] = 0;
        for (int e = 0; e < NE; ++e) { s += g_ecnt[e]; g_off[e + 1] = s; }
    }
}

// ------------------- x split (linear) ------------------------------------
__global__ void split_x_kernel(const float* __restrict__ src) {
    size_t n4 = (size_t)MAXT * HDIM / 4;
    for (size_t i = (size_t)blockIdx.x * blockDim.x + threadIdx.x; i < n4;
         i += (size_t)gridDim.x * blockDim.x) {
        float4 v = ((const float4*)src)[i];
        __nv_bfloat16 h0 = __float2bfloat16_rn(v.x);
        __nv_bfloat16 h1 = __float2bfloat16_rn(v.y);
        __nv_bfloat16 h2 = __float2bfloat16_rn(v.z);
        __nv_bfloat16 h3 = __float2bfloat16_rn(v.w);
        __nv_bfloat16 l0 = __float2bfloat16_rn(v.x - __bfloat162float(h0));
        __nv_bfloat16 l1 = __float2bfloat16_rn(v.y - __bfloat162float(h1));
        __nv_bfloat16 l2 = __float2bfloat16_rn(v.z - __bfloat162float(h2));
        __nv_bfloat16 l3 = __float2bfloat16_rn(v.w - __bfloat162float(h3));
        __nv_bfloat162* H = (__nv_bfloat162*)(g_xh + i * 4);
        __nv_bfloat162* L = (__nv_bfloat162*)(g_xl + i * 4);
        H[0] = __halves2bfloat162(h0, h1); H[1] = __halves2bfloat162(h2, h3);
        L[0] = __halves2bfloat162(l0, l1); L[1] = __halves2bfloat162(l2, l3);
    }
}

// ------------------- weight transpose + split ----------------------------
// src [E][K][N] f32  ->  dst hi/lo [E][N][K] bf16.  sel=1: W1, sel=2: W2.
__global__ void tsplit_w_kernel(const float* __restrict__ src, int sel) {
    int K = (sel == 1) ? HDIM : FDIM;
    int N = (sel == 1) ? FDIM : HDIM;
    __nv_bfloat16* hi = (sel == 1) ? g_w1h : g_w2h;
    __nv_bfloat16* lo = (sel == 1) ? g_w1l : g_w2l;
    __shared__ float t[32][33];
    int e = blockIdx.z;
    int k0 = blockIdx.y * 32, n0 = blockIdx.x * 32;
    const float* s = src + (size_t)e * K * N;
    __nv_bfloat16* hie = hi + (size_t)e * K * N;
    __nv_bfloat16* loe = lo + (size_t)e * K * N;
    for (int i = threadIdx.y; i < 32; i += 8)
        t[i][threadIdx.x] = s[(size_t)(k0 + i) * N + n0 + threadIdx.x];
    __syncthreads();
    for (int i = threadIdx.y; i < 32; i += 8) {
        float v = t[threadIdx.x][i];
        __nv_bfloat16 h = __float2bfloat16_rn(v);
        __nv_bfloat16 l = __float2bfloat16_rn(v - __bfloat162float(h));
        size_t d = (size_t)(n0 + i) * K + k0 + threadIdx.x;
        hie[d] = h; loe[d] = l;
    }
}

// ========================================================================
// GEMM core: CTA 64(M) x 256(N), 4 warps (1M x 4N, warp 64x64), K-tile 32,
// mma.sync m16n8k16 bf16 3-term, 2-stage cp.async ring.
// ========================================================================
__device__ __forceinline__ void load_tile32(
    uint32_t sb, int stage,
    const __nv_bfloat16* a_hi, const __nv_bfloat16* a_lo,
    bool av, long aoff,                     // this thread's A row
    const __nv_bfloat16* b_hi, const __nv_bfloat16* b_lo,
    long boff0, long boff1,                 // this thread's two B rows
    int tid, int kb)
{
    uint32_t buf = sb + stage * STAGEB;
    // A: 64 rows, 64B payload; thread -> (row = tid>>1, half = tid&1)
    int arow = tid >> 1, ah = (tid & 1) * 16;   // element offset 0/16
    uint32_t da = buf + arow * ROWB + ah * 2;
    const __nv_bfloat16* pa = a_hi + aoff + kb + ah;
    const __nv_bfloat16* qa = a_lo + aoff + kb + ah;
    cpa16(da,             pa,     av);
    cpa16(da + 16,        pa + 8, av);
    cpa16(da + A_LO,      qa,     av);
    cpa16(da + A_LO + 16, qa + 8, av);
    // B: 256 rows, 64B payload; thread -> rows {2*tid, 2*tid+1}
    uint32_t db0 = buf + B_HI + (tid * 2) * ROWB;
    uint32_t db1 = db0 + ROWB;
    const __nv_bfloat16* pb0 = b_hi + boff0 + kb;
    const __nv_bfloat16* pb1 = b_hi + boff1 + kb;
    const __nv_bfloat16* qb0 = b_lo + boff0 + kb;
    const __nv_bfloat16* qb1 = b_lo + boff1 + kb;
#pragma unroll
    for (int q = 0; q < 4; ++q) {
        cpa16(db0 + q * 16, pb0 + q * 8, true);
        cpa16(db1 + q * 16, pb1 + q * 8, true);
        cpa16(db0 + (B_LO - B_HI) + q * 16, qb0 + q * 8, true);
        cpa16(db1 + (B_LO - B_HI) + q * 16, qb1 + q * 8, true);
    }
}

__device__ __forceinline__ void compute_stage32(
    uint32_t sb, int stage, int noff, int lane, float acc[4][8][4])
{
    uint32_t base = sb + stage * STAGEB;
    // A frag order: m0=(r0-7,k0-7) m1=(r8-15,k0-7) m2=(r0-7,k8-15) m3=(r8-15,k8-15)
    int arow = lane & 15;
    int akh  = (lane >> 4) << 4;                    // byte 0 / 16
    // B frag order: m0=(n0-7,k0-7) m1=(n0-7,k8-15) m2=(n8-15,k0-7) m3=(n8-15,k8-15)
    int brow = ((lane >> 4) & 1) * 8 + (lane & 7);
    int bkh  = ((lane >> 3) & 1) << 4;              // byte 0 / 16
#pragma unroll
    for (int ks = 0; ks < 2; ++ks) {
        int kby = ks * 32;
        uint32_t fh[4][4], fl[4][4];
#pragma unroll
        for (int i = 0; i < 4; ++i) {
            uint32_t ra = base + (uint32_t)((i * 16 + arow) * ROWB) + kby + akh;
            ldsm4(ra, fh[i]);
            ldsm4(ra + A_LO, fl[i]);
        }
        uint32_t bh[4][4], bl[4][4];
#pragma unroll
        for (int p = 0; p < 4; ++p) {
            uint32_t rb = base + B_HI +
                          (uint32_t)((noff + p * 16 + brow) * ROWB) + kby + bkh;
            ldsm4(rb, bh[p]);
            ldsm4(rb + (B_LO - B_HI), bl[p]);
        }
#pragma unroll
        for (int i = 0; i < 4; ++i)
#pragma unroll
            for (int j = 0; j < 8; ++j) {
                uint32_t* bhj = &bh[j >> 1][(j & 1) * 2];
                uint32_t* blj = &bl[j >> 1][(j & 1) * 2];
                mma_bf16(acc[i][j], fh[i], bhj);
                mma_bf16(acc[i][j], fh[i], blj);
                mma_bf16(acc[i][j], fl[i], bhj);
            }
    }
}

// ------------------- GEMM1: h = gelu(gather(x) @ W1[e]) ------------------
__global__ __launch_bounds__(128) void moe_gemm1() {
    int e = blockIdx.z;
    int n = g_ecnt[e];
    int row0 = blockIdx.y << 6;                     // 64-row tiles
    if (row0 >= n) return;
    int col0 = blockIdx.x << 8;                     // 256-col tiles

    extern __shared__ __align__(16) char smem[];
    uint32_t sb = smem_u32(smem);
    int tid = threadIdx.x, wid = tid >> 5, lane = tid & 31;
    int noff = wid * 64;

    const int* etok = g_etok + e * MAXT;
    int arow_g = row0 + (tid >> 1);
    bool av = arow_g < n;
    long aoff = av ? (long)etok[arow_g] * HDIM : 0;
    long boff0 = (long)(col0 + tid * 2) * HDIM;
    long boff1 = boff0 + HDIM;
    const __nv_bfloat16* Wh = g_w1h + (size_t)e * HDIM * FDIM;
    const __nv_bfloat16* Wl = g_w1l + (size_t)e * HDIM * FDIM;

    float acc[4][8][4];
#pragma unroll
    for (int i = 0; i < 4; ++i)
#pragma unroll
        for (int j = 0; j < 8; ++j)
#pragma unroll
            for (int q = 0; q < 4; ++q) acc[i][j][q] = 0.0f;

    const int KT = HDIM / 32;  // 32
    load_tile32(sb, 0, g_xh, g_xl, av, aoff, Wh, Wl, boff0, boff1, tid, 0);
    cpa_commit();
    for (int kt = 0; kt < KT; ++kt) {
        asm volatile("cp.async.wait_group 0;" ::: "memory");
        __syncthreads();
        if (kt + 1 < KT)
            load_tile32(sb, (kt + 1) & 1, g_xh, g_xl, av, aoff, Wh, Wl,
                        boff0, boff1, tid, (kt + 1) * 32);
        cpa_commit();
        compute_stage32(sb, kt & 1, noff, lane, acc);
        __syncthreads();
    }

    // epilogue: gelu + split -> g_hh/g_hl
    int lane4 = lane >> 2, lanec = (lane & 3) * 2;
    int hbase = g_off[e];
#pragma unroll
    for (int i = 0; i < 4; ++i) {
#pragma unroll
        for (int rr = 0; rr < 2; ++rr) {
            int r = row0 + i * 16 + lane4 + rr * 8;
            if (r < n) {
                size_t base = (size_t)(hbase + r) * FDIM + col0 + noff;
#pragma unroll
                for (int j = 0; j < 8; ++j) {
                    float vA = acc[i][j][rr * 2 + 0];
                    float vB = acc[i][j][rr * 2 + 1];
                    float gA = 0.5f * vA * (1.0f + erff(vA * 0.70710678118654752f));
                    float gB = 0.5f * vB * (1.0f + erff(vB * 0.70710678118654752f));
                    __nv_bfloat16 hA = __float2bfloat16_rn(gA);
                    __nv_bfloat16 hB = __float2bfloat16_rn(gB);
                    __nv_bfloat16 lA = __float2bfloat16_rn(gA - __bfloat162float(hA));
                    __nv_bfloat16 lB = __float2bfloat16_rn(gB - __bfloat162float(hB));
                    size_t o = base + j * 8 + lanec;
                    *(__nv_bfloat162*)(g_hh + o) = __halves2bfloat162(hA, hB);
                    *(__nv_bfloat162*)(g_hl + o) = __halves2bfloat162(lA, lB);
                }
            }
        }
    }
}

// ------------------- GEMM2: out += cw * (h @ W2[e]) ----------------------
__global__ __launch_bounds__(128) void moe_gemm2(float* __restrict__ out) {
    int e = blockIdx.z;
    int n = g_ecnt[e];
    int row0 = blockIdx.y << 6;
    if (row0 >= n) return;
    int col0 = blockIdx.x << 8;

    extern __shared__ __align__(16) char smem[];
    uint32_t sb = smem_u32(smem);
    int tid = threadIdx.x, wid = tid >> 5, lane = tid & 31;
    int noff = wid * 64;

    int hbase = g_off[e];
    int arow_g = row0 + (tid >> 1);
    bool av = arow_g < n;
    long aoff = (long)(hbase + arow_g) * FDIM;
    long boff0 = (long)(col0 + tid * 2) * FDIM;
    long boff1 = boff0 + FDIM;
    const __nv_bfloat16* Wh = g_w2h + (size_t)e * FDIM * HDIM;
    const __nv_bfloat16* Wl = g_w2l + (size_t)e * FDIM * HDIM;

    float acc[4][8][4];
#pragma unroll
    for (int i = 0; i < 4; ++i)
#pragma unroll
        for (int j = 0; j < 8; ++j)
#pragma unroll
            for (int q = 0; q < 4; ++q) acc[i][j][q] = 0.0f;

    const int KT = FDIM / 32;  // 64
    load_tile32(sb, 0, g_hh, g_hl, av, aoff, Wh, Wl, boff0, boff1, tid, 0);
    cpa_commit();
    for (int kt = 0; kt < KT; ++kt) {
        asm volatile("cp.async.wait_group 0;" ::: "memory");
        __syncthreads();
        if (kt + 1 < KT)
            load_tile32(sb, (kt + 1) & 1, g_hh, g_hl, av, aoff, Wh, Wl,
                        boff0, boff1, tid, (kt + 1) * 32);
        cpa_commit();
        compute_stage32(sb, kt & 1, noff, lane, acc);
        __syncthreads();
    }

    // epilogue: weighted atomic scatter into out
    int lane4 = lane >> 2, lanec = (lane & 3) * 2;
#pragma unroll
    for (int i = 0; i < 4; ++i) {
#pragma unroll
        for (int rr = 0; rr < 2; ++rr) {
            int r = row0 + i * 16 + lane4 + rr * 8;
            if (r < n) {
                int   t = g_etok[e * MAXT + r];
                float w = g_ecw [e * MAXT + r];
                float* orow = out + (size_t)t * HDIM + col0 + noff;
#pragma unroll
                for (int j = 0; j < 8; ++j) {
                    atomicAdd(&orow[j * 8 + lanec],     w * acc[i][j][rr * 2 + 0]);
                    atomicAdd(&orow[j * 8 + lanec + 1], w * acc[i][j][rr * 2 + 1]);
                }
            }
        }
    }
}

// ------------------- losses ---------------------------------------------
__global__ void finalize_kernel(float* __restrict__ out, long long out_size, int T) {
    if (blockIdx.x == 0 && threadIdx.x == 0) {
        long long base = (long long)T * HDIM;
        float invT = 1.0f / (float)T;
        float z = g_zacc * invT;
        float tpe0 = (float)g_cnt0 * invT, tpe1 = (float)g_cnt1 * invT;
        float rpp0 = g_sumw0 * invT,       rpp1 = g_sumw1 * invT;
        float aux = 2.0f * (tpe0 * rpp0 + tpe1 * rpp1);
        if (base < out_size)     out[base]     = z;
        if (base + 1 < out_size) out[base + 1] = aux;
    }
}

// ------------------- launch ---------------------------------------------
extern "C" void kernel_launch(void* const* d_in, const int* in_sizes, int n_in,
                              void* d_out, int out_size) {
    const float* x  = (const float*)d_in[0];
    const float* Wg = (const float*)d_in[1];
    const float* W1 = (const float*)d_in[2];
    const float* W2 = (const float*)d_in[3];
    float* out = (float*)d_out;
    int T = in_sizes[0] / HDIM;  // 16384

    cudaFuncSetAttribute(moe_gemm1, cudaFuncAttributeMaxDynamicSharedMemorySize, SMEM_BYTES);
    cudaFuncSetAttribute(moe_gemm2, cudaFuncAttributeMaxDynamicSharedMemorySize, SMEM_BYTES);

    zero_kernel<<<1024, 256>>>(out, (long long)out_size);
    router_kernel<<<(T + 7) / 8, 256>>>(x, Wg, T);
    scan_kernel<<<1, 32>>>();
    split_x_kernel<<<4096, 256>>>(x);
    tsplit_w_kernel<<<dim3(FDIM / 32, HDIM / 32, NE), dim3(32, 8)>>>(W1, 1);
    tsplit_w_kernel<<<dim3(HDIM / 32, FDIM / 32, NE), dim3(32, 8)>>>(W2, 2);
    moe_gemm1<<<dim3(FDIM / 256, MAXT / 64, NE), 128, SMEM_BYTES>>>();
    moe_gemm2<<<dim3(HDIM / 256, MAXT / 64, NE), 128, SMEM_BYTES>>>(out);
    finalize_kernel<<<1, 32>>>(out, (long long)out_size, T);
}

// round 8
// speedup vs baseline: 1.4992x; 1.4992x over previous
#include <cuda_runtime.h>
#include <cuda_fp16.h>
#include <math.h>
#include <stdint.h>

// Shapes fixed by dataset: x[8,2048,1024] f32, Wg[1024,8], W1[8,1024,2048],
// W2[8,2048,1024]. T = 16384 tokens, top-2 of 8 experts.
#define HDIM 1024
#define FDIM 2048
#define NE   8
#define MAXT 16384

// ------------------- device-global scratch ------------------------------
__device__ int   g_ecnt[NE];
__device__ int   g_off[NE + 1];
__device__ int   g_etok[NE * MAXT];
__device__ float g_ecw [NE * MAXT];
__device__ float g_zacc;
__device__ int   g_cnt0, g_cnt1;
__device__ float g_sumw0, g_sumw1;
// fp16 operands. A-side (x, h) split hi/lo; weights single fp16,
// stored TRANSPOSED: w1t [e][F][H], w2t [e][H][F]
__device__ __half g_xh[(size_t)MAXT * HDIM];
__device__ __half g_xl[(size_t)MAXT * HDIM];
__device__ __half g_w1[(size_t)NE * HDIM * FDIM];
__device__ __half g_w2[(size_t)NE * FDIM * HDIM];
// hidden activations (compacted rows), hi/lo, K-contiguous [2T][F]
__device__ __half g_hh[(size_t)2 * MAXT * FDIM];
__device__ __half g_hl[(size_t)2 * MAXT * FDIM];

// ------------------- helpers --------------------------------------------
__device__ __forceinline__ uint32_t smem_u32(const void* p) {
    uint32_t a;
    asm("{ .reg .u64 t; cvta.to.shared.u64 t, %1; cvt.u32.u64 %0, t; }"
        : "=r"(a) : "l"(p));
    return a;
}
__device__ __forceinline__ void cpa16(uint32_t dst, const void* src, bool valid) {
    int sz = valid ? 16 : 0;
    asm volatile("cp.async.cg.shared.global [%0], [%1], 16, %2;"
                 :: "r"(dst), "l"(src), "r"(sz) : "memory");
}
__device__ __forceinline__ void cpa_commit() {
    asm volatile("cp.async.commit_group;" ::: "memory");
}
__device__ __forceinline__ void mma_f16(float* c, const uint32_t* a, const uint32_t* b) {
    asm volatile(
        "mma.sync.aligned.m16n8k16.row.col.f32.f16.f16.f32 "
        "{%0,%1,%2,%3}, {%4,%5,%6,%7}, {%8,%9}, {%0,%1,%2,%3};"
        : "+f"(c[0]), "+f"(c[1]), "+f"(c[2]), "+f"(c[3])
        : "r"(a[0]), "r"(a[1]), "r"(a[2]), "r"(a[3]), "r"(b[0]), "r"(b[1]));
}
__device__ __forceinline__ void ldsm4(uint32_t addr, uint32_t* r) {
    asm volatile("ldmatrix.sync.aligned.m8n8.x4.shared.b16 {%0,%1,%2,%3}, [%4];"
                 : "=r"(r[0]), "=r"(r[1]), "=r"(r[2]), "=r"(r[3]) : "r"(addr));
}

// SMEM tile geometry: K-tile 16, rows padded to 48 B (16B-aligned cp.async,
// ldmatrix banks 12r mod 32 all distinct -> conflict-free).
#define ROWB 48
#define SEGB 6144            // 128 rows * 48 B
#define STAGEB 18432         // Ah | Al | B
#define NSTAGE 4
#define SMEM_BYTES (NSTAGE * STAGEB)   // 73728

// ------------------- zero / reset ---------------------------------------
__global__ void zero_kernel(float* __restrict__ out, long long n) {
    long long i = (long long)blockIdx.x * blockDim.x + threadIdx.x;
    long long stride = (long long)gridDim.x * blockDim.x;
    for (; i < n; i += stride) out[i] = 0.0f;
    if (blockIdx.x == 0) {
        if (threadIdx.x == 0) {
            g_zacc = 0.0f; g_cnt0 = 0; g_cnt1 = 0;
            g_sumw0 = 0.0f; g_sumw1 = 0.0f;
        }
        if (threadIdx.x < NE) g_ecnt[threadIdx.x] = 0;
    }
}

// ------------------- router ---------------------------------------------
__global__ void router_kernel(const float* __restrict__ x,
                              const float* __restrict__ Wg, int T) {
    int warp = (blockIdx.x * blockDim.x + threadIdx.x) >> 5;
    int lane = threadIdx.x & 31;
    if (warp >= T) return;
    const float* xr = x + (size_t)warp * HDIM;

    float acc[NE];
#pragma unroll
    for (int e = 0; e < NE; ++e) acc[e] = 0.0f;
    for (int i = lane; i < HDIM; i += 32) {
        float xv = xr[i];
        float4 w0 = *(const float4*)(Wg + (size_t)i * NE);
        float4 w1 = *(const float4*)(Wg + (size_t)i * NE + 4);
        acc[0] += xv * w0.x; acc[1] += xv * w0.y;
        acc[2] += xv * w0.z; acc[3] += xv * w0.w;
        acc[4] += xv * w1.x; acc[5] += xv * w1.y;
        acc[6] += xv * w1.z; acc[7] += xv * w1.w;
    }
#pragma unroll
    for (int off = 16; off > 0; off >>= 1)
#pragma unroll
        for (int e = 0; e < NE; ++e)
            acc[e] += __shfl_xor_sync(0xFFFFFFFFu, acc[e], off);

    if (lane == 0) {
        float m = acc[0];
#pragma unroll
        for (int e = 1; e < NE; ++e) m = fmaxf(m, acc[e]);
        float p[NE], s = 0.0f;
#pragma unroll
        for (int e = 0; e < NE; ++e) { p[e] = __expf(acc[e] - m); s += p[e]; }
        float lse = m + logf(s);
        atomicAdd(&g_zacc, lse * lse);

        int i0 = 0;
#pragma unroll
        for (int e = 1; e < NE; ++e) if (p[e] > p[i0]) i0 = e;
        int i1 = (i0 == 0) ? 1 : 0;
#pragma unroll
        for (int e = 0; e < NE; ++e) if (e != i0 && p[e] > p[i1]) i1 = e;
        float w0 = p[i0] / s, w1 = p[i1] / s;

        atomicAdd(&g_sumw0, w0);
        atomicAdd(&g_sumw1, w1);
        if (i0 == 0 || i1 == 0) atomicAdd(&g_cnt0, 1);
        if (i0 == 1 || i1 == 1) atomicAdd(&g_cnt1, 1);

        int p0 = atomicAdd(&g_ecnt[i0], 1);
        g_etok[i0 * MAXT + p0] = warp; g_ecw[i0 * MAXT + p0] = w0;
        int p1 = atomicAdd(&g_ecnt[i1], 1);
        g_etok[i1 * MAXT + p1] = warp; g_ecw[i1 * MAXT + p1] = w1;
    }
}

__global__ void scan_kernel() {
    if (threadIdx.x == 0) {
        int s = 0; g_off[0] = 0;
        for (int e = 0; e < NE; ++e) { s += g_ecnt[e]; g_off[e + 1] = s; }
    }
}

// ------------------- x split (linear, fp16 hi/lo) -------------------------
__global__ void split_x_kernel(const float* __restrict__ src) {
    size_t n4 = (size_t)MAXT * HDIM / 4;
    for (size_t i = (size_t)blockIdx.x * blockDim.x + threadIdx.x; i < n4;
         i += (size_t)gridDim.x * blockDim.x) {
        float4 v = ((const float4*)src)[i];
        __half h0 = __float2half_rn(v.x);
        __half h1 = __float2half_rn(v.y);
        __half h2 = __float2half_rn(v.z);
        __half h3 = __float2half_rn(v.w);
        __half l0 = __float2half_rn(v.x - __half2float(h0));
        __half l1 = __float2half_rn(v.y - __half2float(h1));
        __half l2 = __float2half_rn(v.z - __half2float(h2));
        __half l3 = __float2half_rn(v.w - __half2float(h3));
        __half2* H = (__half2*)(g_xh + i * 4);
        __half2* L = (__half2*)(g_xl + i * 4);
        H[0] = __halves2half2(h0, h1); H[1] = __halves2half2(h2, h3);
        L[0] = __halves2half2(l0, l1); L[1] = __halves2half2(l2, l3);
    }
}

// ------------------- weight transpose (single fp16) -----------------------
// src [E][K][N] f32  ->  dst [E][N][K] fp16.  sel=1: W1, sel=2: W2.
__global__ void tsplit_w_kernel(const float* __restrict__ src, int sel) {
    int K = (sel == 1) ? HDIM : FDIM;
    int N = (sel == 1) ? FDIM : HDIM;
    __half* dst = (sel == 1) ? g_w1 : g_w2;
    __shared__ float t[32][33];
    int e = blockIdx.z;
    int k0 = blockIdx.y * 32, n0 = blockIdx.x * 32;
    const float* s = src + (size_t)e * K * N;
    __half* de = dst + (size_t)e * K * N;
    for (int i = threadIdx.y; i < 32; i += 8)
        t[i][threadIdx.x] = s[(size_t)(k0 + i) * N + n0 + threadIdx.x];
    __syncthreads();
    for (int i = threadIdx.y; i < 32; i += 8) {
        float v = t[threadIdx.x][i];
        de[(size_t)(n0 + i) * K + k0 + threadIdx.x] = __float2half_rn(v);
    }
}

// ========================================================================
// GEMM core: CTA 128x128, 4 warps (warp tile 64x64), K-tile 16,
// mma.sync m16n8k16 fp16 2-term (Ah*B + Al*B), 4-stage ring, 1 sync/iter.
// ========================================================================
__device__ __forceinline__ void load_tile16(
    uint32_t sb, int stage,
    const __half* a_hi, const __half* a_lo, bool av, long aoff,
    const __half* b, long boff,
    int tid, int kb)
{
    uint32_t buf = sb + stage * STAGEB;
    uint32_t d = buf + tid * ROWB;
    const __half* pa = a_hi + aoff + kb;
    const __half* qa = a_lo + aoff + kb;
    const __half* pb = b + boff + kb;
    cpa16(d,                 pa,     av);
    cpa16(d + 16,            pa + 8, av);
    cpa16(d + SEGB,          qa,     av);
    cpa16(d + SEGB + 16,     qa + 8, av);
    cpa16(d + 2 * SEGB,      pb,     true);
    cpa16(d + 2 * SEGB + 16, pb + 8, true);
}

__device__ __forceinline__ void compute_stage16(
    uint32_t sb, int stage, int moff, int noff, int lane,
    float acc[4][8][4])
{
    uint32_t base = sb + stage * STAGEB;
    // A fragment: m0=(r0-7,k0-7) m1=(r8-15,k0-7) m2=(r0-7,k8-15) m3=(r8-15,k8-15)
    int arow = lane & 15;
    int akh  = (lane >> 4) << 4;                    // byte offset 0 / 16
    // B fragment: m0=(n0-7,k0-7) m1=(n0-7,k8-15) m2=(n8-15,k0-7) m3=(n8-15,k8-15)
    int brow = ((lane >> 4) & 1) * 8 + (lane & 7);
    int bkh  = ((lane >> 3) & 1) << 4;              // byte offset 0 / 16
    uint32_t fh[4][4], fl[4][4];
#pragma unroll
    for (int i = 0; i < 4; ++i) {
        uint32_t ra = base + (uint32_t)((moff + i * 16 + arow) * ROWB) + akh;
        ldsm4(ra, fh[i]);
        ldsm4(ra + SEGB, fl[i]);
    }
    uint32_t bb[4][4];
#pragma unroll
    for (int p = 0; p < 4; ++p) {
        uint32_t rb = base + 2 * SEGB +
                      (uint32_t)((noff + p * 16 + brow) * ROWB) + bkh;
        ldsm4(rb, bb[p]);
    }
#pragma unroll
    for (int i = 0; i < 4; ++i)
#pragma unroll
        for (int j = 0; j < 8; ++j) {
            uint32_t* bj = &bb[j >> 1][(j & 1) * 2];
            mma_f16(acc[i][j], fh[i], bj);
            mma_f16(acc[i][j], fl[i], bj);
        }
}

// ------------------- GEMM1: h = gelu(gather(x) @ W1[e]) ------------------
__global__ __launch_bounds__(128) void moe_gemm1() {
    int e = blockIdx.z;
    int n = g_ecnt[e];
    int row0 = blockIdx.y << 7;
    if (row0 >= n) return;
    int col0 = blockIdx.x << 7;

    extern __shared__ __align__(16) char smem[];
    uint32_t sb = smem_u32(smem);
    int tid = threadIdx.x, wid = tid >> 5, lane = tid & 31;
    int moff = (wid >> 1) * 64, noff = (wid & 1) * 64;

    const int* etok = g_etok + e * MAXT;
    bool av = (row0 + tid) < n;
    long aoff = av ? (long)etok[row0 + tid] * HDIM : 0;
    long boff = (long)(col0 + tid) * HDIM;
    const __half* W = g_w1 + (size_t)e * HDIM * FDIM;

    float acc[4][8][4];
#pragma unroll
    for (int i = 0; i < 4; ++i)
#pragma unroll
        for (int j = 0; j < 8; ++j)
#pragma unroll
            for (int q = 0; q < 4; ++q) acc[i][j][q] = 0.0f;

    const int KT = HDIM / 16;  // 64
    load_tile16(sb, 0, g_xh, g_xl, av, aoff, W, boff, tid, 0);
    cpa_commit();
    load_tile16(sb, 1, g_xh, g_xl, av, aoff, W, boff, tid, 16);
    cpa_commit();
    load_tile16(sb, 2, g_xh, g_xl, av, aoff, W, boff, tid, 32);
    cpa_commit();
    for (int kt = 0; kt < KT; ++kt) {
        asm volatile("cp.async.wait_group 2;" ::: "memory");
        __syncthreads();
        if (kt + 3 < KT)
            load_tile16(sb, (kt + 3) & 3, g_xh, g_xl, av, aoff, W, boff,
                        tid, (kt + 3) * 16);
        cpa_commit();
        compute_stage16(sb, kt & 3, moff, noff, lane, acc);
    }

    // epilogue: gelu + fp16 hi/lo split -> g_hh/g_hl
    int lane4 = lane >> 2, lanec = (lane & 3) * 2;
    int hbase = g_off[e];
#pragma unroll
    for (int i = 0; i < 4; ++i) {
#pragma unroll
        for (int rr = 0; rr < 2; ++rr) {
            int r = row0 + moff + i * 16 + lane4 + rr * 8;
            if (r < n) {
                size_t base = (size_t)(hbase + r) * FDIM + col0 + noff;
#pragma unroll
                for (int j = 0; j < 8; ++j) {
                    float vA = acc[i][j][rr * 2 + 0];
                    float vB = acc[i][j][rr * 2 + 1];
                    float gA = 0.5f * vA * (1.0f + erff(vA * 0.70710678118654752f));
                    float gB = 0.5f * vB * (1.0f + erff(vB * 0.70710678118654752f));
                    __half hA = __float2half_rn(gA);
                    __half hB = __float2half_rn(gB);
                    __half lA = __float2half_rn(gA - __half2float(hA));
                    __half lB = __float2half_rn(gB - __half2float(hB));
                    size_t o = base + j * 8 + lanec;
                    *(__half2*)(g_hh + o) = __halves2half2(hA, hB);
                    *(__half2*)(g_hl + o) = __halves2half2(lA, lB);
                }
            }
        }
    }
}

// ------------------- GEMM2: out += cw * (h @ W2[e]) ----------------------
__global__ __launch_bounds__(128) void moe_gemm2(float* __restrict__ out) {
    int e = blockIdx.z;
    int n = g_ecnt[e];
    int row0 = blockIdx.y << 7;
    if (row0 >= n) return;
    int col0 = blockIdx.x << 7;

    extern __shared__ __align__(16) char smem[];
    uint32_t sb = smem_u32(smem);
    int tid = threadIdx.x, wid = tid >> 5, lane = tid & 31;
    int moff = (wid >> 1) * 64, noff = (wid & 1) * 64;

    int hbase = g_off[e];
    bool av = (row0 + tid) < n;
    long aoff = (long)(hbase + row0 + tid) * FDIM;
    long boff = (long)(col0 + tid) * FDIM;
    const __half* W = g_w2 + (size_t)e * FDIM * HDIM;

    float acc[4][8][4];
#pragma unroll
    for (int i = 0; i < 4; ++i)
#pragma unroll
        for (int j = 0; j < 8; ++j)
#pragma unroll
            for (int q = 0; q < 4; ++q) acc[i][j][q] = 0.0f;

    const int KT = FDIM / 16;  // 128
    load_tile16(sb, 0, g_hh, g_hl, av, aoff, W, boff, tid, 0);
    cpa_commit();
    load_tile16(sb, 1, g_hh, g_hl, av, aoff, W, boff, tid, 16);
    cpa_commit();
    load_tile16(sb, 2, g_hh, g_hl, av, aoff, W, boff, tid, 32);
    cpa_commit();
    for (int kt = 0; kt < KT; ++kt) {
        asm volatile("cp.async.wait_group 2;" ::: "memory");
        __syncthreads();
        if (kt + 3 < KT)
            load_tile16(sb, (kt + 3) & 3, g_hh, g_hl, av, aoff, W, boff,
                        tid, (kt + 3) * 16);
        cpa_commit();
        compute_stage16(sb, kt & 3, moff, noff, lane, acc);
    }

    // epilogue: weighted atomic scatter into out
    int lane4 = lane >> 2, lanec = (lane & 3) * 2;
#pragma unroll
    for (int i = 0; i < 4; ++i) {
#pragma unroll
        for (int rr = 0; rr < 2; ++rr) {
            int r = row0 + moff + i * 16 + lane4 + rr * 8;
            if (r < n) {
                int   t = g_etok[e * MAXT + r];
                float w = g_ecw [e * MAXT + r];
                float* orow = out + (size_t)t * HDIM + col0 + noff;
#pragma unroll
                for (int j = 0; j < 8; ++j) {
                    atomicAdd(&orow[j * 8 + lanec],     w * acc[i][j][rr * 2 + 0]);
                    atomicAdd(&orow[j * 8 + lanec + 1], w * acc[i][j][rr * 2 + 1]);
                }
            }
        }
    }
}

// ------------------- losses ---------------------------------------------
__global__ void finalize_kernel(float* __restrict__ out, long long out_size, int T) {
    if (blockIdx.x == 0 && threadIdx.x == 0) {
        long long base = (long long)T * HDIM;
        float invT = 1.0f / (float)T;
        float z = g_zacc * invT;
        float tpe0 = (float)g_cnt0 * invT, tpe1 = (float)g_cnt1 * invT;
        float rpp0 = g_sumw0 * invT,       rpp1 = g_sumw1 * invT;
        float aux = 2.0f * (tpe0 * rpp0 + tpe1 * rpp1);
        if (base < out_size)     out[base]     = z;
        if (base + 1 < out_size) out[base + 1] = aux;
    }
}

// ------------------- launch ---------------------------------------------
extern "C" void kernel_launch(void* const* d_in, const int* in_sizes, int n_in,
                              void* d_out, int out_size) {
    const float* x  = (const float*)d_in[0];
    const float* Wg = (const float*)d_in[1];
    const float* W1 = (const float*)d_in[2];
    const float* W2 = (const float*)d_in[3];
    float* out = (float*)d_out;
    int T = in_sizes[0] / HDIM;  // 16384

    cudaFuncSetAttribute(moe_gemm1, cudaFuncAttributeMaxDynamicSharedMemorySize, SMEM_BYTES);
    cudaFuncSetAttribute(moe_gemm2, cudaFuncAttributeMaxDynamicSharedMemorySize, SMEM_BYTES);

    zero_kernel<<<1024, 256>>>(out, (long long)out_size);
    router_kernel<<<(T + 7) / 8, 256>>>(x, Wg, T);
    scan_kernel<<<1, 32>>>();
    split_x_kernel<<<4096, 256>>>(x);
    tsplit_w_kernel<<<dim3(FDIM / 32, HDIM / 32, NE), dim3(32, 8)>>>(W1, 1);
    tsplit_w_kernel<<<dim3(HDIM / 32, FDIM / 32, NE), dim3(32, 8)>>>(W2, 2);
    moe_gemm1<<<dim3(FDIM / 128, MAXT / 128, NE), 128, SMEM_BYTES>>>();
    moe_gemm2<<<dim3(HDIM / 128, MAXT / 128, NE), 128, SMEM_BYTES>>>(out);
    finalize_kernel<<<1, 32>>>(out, (long long)out_size, T);
}

// round 9
// speedup vs baseline: 2.4981x; 1.6663x over previous
#include <cuda_runtime.h>
#include <cuda_fp16.h>
#include <math.h>
#include <stdint.h>

// Shapes fixed by dataset: x[8,2048,1024] f32, Wg[1024,8], W1[8,1024,2048],
// W2[8,2048,1024]. T = 16384 tokens, top-2 of 8 experts.
#define HDIM 1024
#define FDIM 2048
#define NE   8
#define MAXT 16384

// ------------------- device-global scratch ------------------------------
__device__ int   g_ecnt[NE];
__device__ int   g_off[NE + 1];
__device__ int   g_etok[NE * MAXT];
__device__ float g_ecw [NE * MAXT];
__device__ float g_zacc;
__device__ int   g_cnt0, g_cnt1;
__device__ float g_sumw0, g_sumw1;
// fp16 operands (single precision level). Weights stored TRANSPOSED:
// w1t [e][F][H], w2t [e][H][F]
__device__ __half g_x [(size_t)MAXT * HDIM];
__device__ __half g_w1[(size_t)NE * HDIM * FDIM];
__device__ __half g_w2[(size_t)NE * FDIM * HDIM];
// hidden activations (compacted rows), K-contiguous [2T][F]
__device__ __half g_h [(size_t)2 * MAXT * FDIM];

// ------------------- helpers --------------------------------------------
__device__ __forceinline__ uint32_t smem_u32(const void* p) {
    uint32_t a;
    asm("{ .reg .u64 t; cvta.to.shared.u64 t, %1; cvt.u32.u64 %0, t; }"
        : "=r"(a) : "l"(p));
    return a;
}
__device__ __forceinline__ void cpa16(uint32_t dst, const void* src, bool valid) {
    int sz = valid ? 16 : 0;
    asm volatile("cp.async.cg.shared.global [%0], [%1], 16, %2;"
                 :: "r"(dst), "l"(src), "r"(sz) : "memory");
}
__device__ __forceinline__ void cpa_commit() {
    asm volatile("cp.async.commit_group;" ::: "memory");
}
__device__ __forceinline__ void mma_f16(float* c, const uint32_t* a, const uint32_t* b) {
    asm volatile(
        "mma.sync.aligned.m16n8k16.row.col.f32.f16.f16.f32 "
        "{%0,%1,%2,%3}, {%4,%5,%6,%7}, {%8,%9}, {%0,%1,%2,%3};"
        : "+f"(c[0]), "+f"(c[1]), "+f"(c[2]), "+f"(c[3])
        : "r"(a[0]), "r"(a[1]), "r"(a[2]), "r"(a[3]), "r"(b[0]), "r"(b[1]));
}
__device__ __forceinline__ void ldsm4(uint32_t addr, uint32_t* r) {
    asm volatile("ldmatrix.sync.aligned.m8n8.x4.shared.b16 {%0,%1,%2,%3}, [%4];"
                 : "=r"(r[0]), "=r"(r[1]), "=r"(r[2]), "=r"(r[3]) : "r"(addr));
}

// SMEM tile geometry: K-tile 16, rows padded to 48 B (16B-aligned cp.async,
// ldmatrix banks 12r mod 32 all distinct -> conflict-free).
#define ROWB 48
#define SEGB 6144            // 128 rows * 48 B
#define STAGEB 12288         // A | B
#define NSTAGE 4
#define SMEM_BYTES (NSTAGE * STAGEB)   // 49152

// ------------------- zero / reset ---------------------------------------
__global__ void zero_kernel(float* __restrict__ out, long long n) {
    long long i = (long long)blockIdx.x * blockDim.x + threadIdx.x;
    long long stride = (long long)gridDim.x * blockDim.x;
    for (; i < n; i += stride) out[i] = 0.0f;
    if (blockIdx.x == 0) {
        if (threadIdx.x == 0) {
            g_zacc = 0.0f; g_cnt0 = 0; g_cnt1 = 0;
            g_sumw0 = 0.0f; g_sumw1 = 0.0f;
        }
        if (threadIdx.x < NE) g_ecnt[threadIdx.x] = 0;
    }
}

// ------------------- router ---------------------------------------------
__global__ void router_kernel(const float* __restrict__ x,
                              const float* __restrict__ Wg, int T) {
    int warp = (blockIdx.x * blockDim.x + threadIdx.x) >> 5;
    int lane = threadIdx.x & 31;
    if (warp >= T) return;
    const float* xr = x + (size_t)warp * HDIM;

    float acc[NE];
#pragma unroll
    for (int e = 0; e < NE; ++e) acc[e] = 0.0f;
    for (int i = lane; i < HDIM; i += 32) {
        float xv = xr[i];
        float4 w0 = *(const float4*)(Wg + (size_t)i * NE);
        float4 w1 = *(const float4*)(Wg + (size_t)i * NE + 4);
        acc[0] += xv * w0.x; acc[1] += xv * w0.y;
        acc[2] += xv * w0.z; acc[3] += xv * w0.w;
        acc[4] += xv * w1.x; acc[5] += xv * w1.y;
        acc[6] += xv * w1.z; acc[7] += xv * w1.w;
    }
#pragma unroll
    for (int off = 16; off > 0; off >>= 1)
#pragma unroll
        for (int e = 0; e < NE; ++e)
            acc[e] += __shfl_xor_sync(0xFFFFFFFFu, acc[e], off);

    if (lane == 0) {
        float m = acc[0];
#pragma unroll
        for (int e = 1; e < NE; ++e) m = fmaxf(m, acc[e]);
        float p[NE], s = 0.0f;
#pragma unroll
        for (int e = 0; e < NE; ++e) { p[e] = __expf(acc[e] - m); s += p[e]; }
        float lse = m + logf(s);
        atomicAdd(&g_zacc, lse * lse);

        int i0 = 0;
#pragma unroll
        for (int e = 1; e < NE; ++e) if (p[e] > p[i0]) i0 = e;
        int i1 = (i0 == 0) ? 1 : 0;
#pragma unroll
        for (int e = 0; e < NE; ++e) if (e != i0 && p[e] > p[i1]) i1 = e;
        float w0 = p[i0] / s, w1 = p[i1] / s;

        atomicAdd(&g_sumw0, w0);
        atomicAdd(&g_sumw1, w1);
        if (i0 == 0 || i1 == 0) atomicAdd(&g_cnt0, 1);
        if (i0 == 1 || i1 == 1) atomicAdd(&g_cnt1, 1);

        int p0 = atomicAdd(&g_ecnt[i0], 1);
        g_etok[i0 * MAXT + p0] = warp; g_ecw[i0 * MAXT + p0] = w0;
        int p1 = atomicAdd(&g_ecnt[i1], 1);
        g_etok[i1 * MAXT + p1] = warp; g_ecw[i1 * MAXT + p1] = w1;
    }
}

__global__ void scan_kernel() {
    if (threadIdx.x == 0) {
        int s = 0; g_off[0] = 0;
        for (int e = 0; e < NE; ++e) { s += g_ecnt[e]; g_off[e + 1] = s; }
    }
}

// ------------------- x convert (linear, fp16) -----------------------------
__global__ void cvt_x_kernel(const float* __restrict__ src) {
    size_t n4 = (size_t)MAXT * HDIM / 4;
    for (size_t i = (size_t)blockIdx.x * blockDim.x + threadIdx.x; i < n4;
         i += (size_t)gridDim.x * blockDim.x) {
        float4 v = ((const float4*)src)[i];
        __half2* H = (__half2*)(g_x + i * 4);
        H[0] = __halves2half2(__float2half_rn(v.x), __float2half_rn(v.y));
        H[1] = __halves2half2(__float2half_rn(v.z), __float2half_rn(v.w));
    }
}

// ------------------- weight transpose (fp16) ------------------------------
// src [E][K][N] f32  ->  dst [E][N][K] fp16.  sel=1: W1, sel=2: W2.
__global__ void tsplit_w_kernel(const float* __restrict__ src, int sel) {
    int K = (sel == 1) ? HDIM : FDIM;
    int N = (sel == 1) ? FDIM : HDIM;
    __half* dst = (sel == 1) ? g_w1 : g_w2;
    __shared__ float t[32][33];
    int e = blockIdx.z;
    int k0 = blockIdx.y * 32, n0 = blockIdx.x * 32;
    const float* s = src + (size_t)e * K * N;
    __half* de = dst + (size_t)e * K * N;
    for (int i = threadIdx.y; i < 32; i += 8)
        t[i][threadIdx.x] = s[(size_t)(k0 + i) * N + n0 + threadIdx.x];
    __syncthreads();
    for (int i = threadIdx.y; i < 32; i += 8) {
        float v = t[threadIdx.x][i];
        de[(size_t)(n0 + i) * K + k0 + threadIdx.x] = __float2half_rn(v);
    }
}

// ========================================================================
// GEMM core: CTA 128x128, 4 warps (warp tile 64x64), K-tile 16,
// mma.sync m16n8k16 fp16 single-term, 4-stage ring, 1 sync/iter.
// ========================================================================
__device__ __forceinline__ void load_tile16(
    uint32_t sb, int stage,
    const __half* a, bool av, long aoff,
    const __half* b, long boff,
    int tid, int kb)
{
    uint32_t buf = sb + stage * STAGEB;
    uint32_t d = buf + tid * ROWB;
    const __half* pa = a + aoff + kb;
    const __half* pb = b + boff + kb;
    cpa16(d,              pa,     av);
    cpa16(d + 16,         pa + 8, av);
    cpa16(d + SEGB,       pb,     true);
    cpa16(d + SEGB + 16,  pb + 8, true);
}

__device__ __forceinline__ void compute_stage16(
    uint32_t sb, int stage, int moff, int noff, int lane,
    float acc[4][8][4])
{
    uint32_t base = sb + stage * STAGEB;
    // A fragment: m0=(r0-7,k0-7) m1=(r8-15,k0-7) m2=(r0-7,k8-15) m3=(r8-15,k8-15)
    int arow = lane & 15;
    int akh  = (lane >> 4) << 4;                    // byte offset 0 / 16
    // B fragment: m0=(n0-7,k0-7) m1=(n0-7,k8-15) m2=(n8-15,k0-7) m3=(n8-15,k8-15)
    int brow = ((lane >> 4) & 1) * 8 + (lane & 7);
    int bkh  = ((lane >> 3) & 1) << 4;              // byte offset 0 / 16
    uint32_t fa[4][4];
#pragma unroll
    for (int i = 0; i < 4; ++i) {
        uint32_t ra = base + (uint32_t)((moff + i * 16 + arow) * ROWB) + akh;
        ldsm4(ra, fa[i]);
    }
    uint32_t bb[4][4];
#pragma unroll
    for (int p = 0; p < 4; ++p) {
        uint32_t rb = base + SEGB +
                      (uint32_t)((noff + p * 16 + brow) * ROWB) + bkh;
        ldsm4(rb, bb[p]);
    }
#pragma unroll
    for (int i = 0; i < 4; ++i)
#pragma unroll
        for (int j = 0; j < 8; ++j) {
            uint32_t* bj = &bb[j >> 1][(j & 1) * 2];
            mma_f16(acc[i][j], fa[i], bj);
        }
}

// ------------------- GEMM1: h = gelu(gather(x) @ W1[e]) ------------------
__global__ __launch_bounds__(128) void moe_gemm1() {
    int e = blockIdx.z;
    int n = g_ecnt[e];
    int row0 = blockIdx.y << 7;
    if (row0 >= n) return;
    int col0 = blockIdx.x << 7;

    extern __shared__ __align__(16) char smem[];
    uint32_t sb = smem_u32(smem);
    int tid = threadIdx.x, wid = tid >> 5, lane = tid & 31;
    int moff = (wid >> 1) * 64, noff = (wid & 1) * 64;

    const int* etok = g_etok + e * MAXT;
    bool av = (row0 + tid) < n;
    long aoff = av ? (long)etok[row0 + tid] * HDIM : 0;
    long boff = (long)(col0 + tid) * HDIM;
    const __half* W = g_w1 + (size_t)e * HDIM * FDIM;

    float acc[4][8][4];
#pragma unroll
    for (int i = 0; i < 4; ++i)
#pragma unroll
        for (int j = 0; j < 8; ++j)
#pragma unroll
            for (int q = 0; q < 4; ++q) acc[i][j][q] = 0.0f;

    const int KT = HDIM / 16;  // 64
    load_tile16(sb, 0, g_x, av, aoff, W, boff, tid, 0);
    cpa_commit();
    load_tile16(sb, 1, g_x, av, aoff, W, boff, tid, 16);
    cpa_commit();
    load_tile16(sb, 2, g_x, av, aoff, W, boff, tid, 32);
    cpa_commit();
    for (int kt = 0; kt < KT; ++kt) {
        asm volatile("cp.async.wait_group 2;" ::: "memory");
        __syncthreads();
        if (kt + 3 < KT)
            load_tile16(sb, (kt + 3) & 3, g_x, av, aoff, W, boff,
                        tid, (kt + 3) * 16);
        cpa_commit();
        compute_stage16(sb, kt & 3, moff, noff, lane, acc);
    }

    // epilogue: gelu -> fp16 h
    int lane4 = lane >> 2, lanec = (lane & 3) * 2;
    int hbase = g_off[e];
#pragma unroll
    for (int i = 0; i < 4; ++i) {
#pragma unroll
        for (int rr = 0; rr < 2; ++rr) {
            int r = row0 + moff + i * 16 + lane4 + rr * 8;
            if (r < n) {
                size_t base = (size_t)(hbase + r) * FDIM + col0 + noff;
#pragma unroll
                for (int j = 0; j < 8; ++j) {
                    float vA = acc[i][j][rr * 2 + 0];
                    float vB = acc[i][j][rr * 2 + 1];
                    float gA = 0.5f * vA * (1.0f + erff(vA * 0.70710678118654752f));
                    float gB = 0.5f * vB * (1.0f + erff(vB * 0.70710678118654752f));
                    *(__half2*)(g_h + base + j * 8 + lanec) =
                        __halves2half2(__float2half_rn(gA), __float2half_rn(gB));
                }
            }
        }
    }
}

// ------------------- GEMM2: out += cw * (h @ W2[e]) ----------------------
__global__ __launch_bounds__(128) void moe_gemm2(float* __restrict__ out) {
    int e = blockIdx.z;
    int n = g_ecnt[e];
    int row0 = blockIdx.y << 7;
    if (row0 >= n) return;
    int col0 = blockIdx.x << 7;

    extern __shared__ __align__(16) char smem[];
    uint32_t sb = smem_u32(smem);
    int tid = threadIdx.x, wid = tid >> 5, lane = tid & 31;
    int moff = (wid >> 1) * 64, noff = (wid & 1) * 64;

    int hbase = g_off[e];
    bool av = (row0 + tid) < n;
    long aoff = (long)(hbase + row0 + tid) * FDIM;
    long boff = (long)(col0 + tid) * FDIM;
    const __half* W = g_w2 + (size_t)e * FDIM * HDIM;

    float acc[4][8][4];
#pragma unroll
    for (int i = 0; i < 4; ++i)
#pragma unroll
        for (int j = 0; j < 8; ++j)
#pragma unroll
            for (int q = 0; q < 4; ++q) acc[i][j][q] = 0.0f;

    const int KT = FDIM / 16;  // 128
    load_tile16(sb, 0, g_h, av, aoff, W, boff, tid, 0);
    cpa_commit();
    load_tile16(sb, 1, g_h, av, aoff, W, boff, tid, 16);
    cpa_commit();
    load_tile16(sb, 2, g_h, av, aoff, W, boff, tid, 32);
    cpa_commit();
    for (int kt = 0; kt < KT; ++kt) {
        asm volatile("cp.async.wait_group 2;" ::: "memory");
        __syncthreads();
        if (kt + 3 < KT)
            load_tile16(sb, (kt + 3) & 3, g_h, av, aoff, W, boff,
                        tid, (kt + 3) * 16);
        cpa_commit();
        compute_stage16(sb, kt & 3, moff, noff, lane, acc);
    }

    // epilogue: weighted atomic scatter into out
    int lane4 = lane >> 2, lanec = (lane & 3) * 2;
#pragma unroll
    for (int i = 0; i < 4; ++i) {
#pragma unroll
        for (int rr = 0; rr < 2; ++rr) {
            int r = row0 + moff + i * 16 + lane4 + rr * 8;
            if (r < n) {
                int   t = g_etok[e * MAXT + r];
                float w = g_ecw [e * MAXT + r];
                float* orow = out + (size_t)t * HDIM + col0 + noff;
#pragma unroll
                for (int j = 0; j < 8; ++j) {
                    atomicAdd(&orow[j * 8 + lanec],     w * acc[i][j][rr * 2 + 0]);
                    atomicAdd(&orow[j * 8 + lanec + 1], w * acc[i][j][rr * 2 + 1]);
                }
            }
        }
    }
}

// ------------------- losses ---------------------------------------------
__global__ void finalize_kernel(float* __restrict__ out, long long out_size, int T) {
    if (blockIdx.x == 0 && threadIdx.x == 0) {
        long long base = (long long)T * HDIM;
        float invT = 1.0f / (float)T;
        float z = g_zacc * invT;
        float tpe0 = (float)g_cnt0 * invT, tpe1 = (float)g_cnt1 * invT;
        float rpp0 = g_sumw0 * invT,       rpp1 = g_sumw1 * invT;
        float aux = 2.0f * (tpe0 * rpp0 + tpe1 * rpp1);
        if (base < out_size)     out[base]     = z;
        if (base + 1 < out_size) out[base + 1] = aux;
    }
}

// ------------------- launch ---------------------------------------------
extern "C" void kernel_launch(void* const* d_in, const int* in_sizes, int n_in,
                              void* d_out, int out_size) {
    const float* x  = (const float*)d_in[0];
    const float* Wg = (const float*)d_in[1];
    const float* W1 = (const float*)d_in[2];
    const float* W2 = (const float*)d_in[3];
    float* out = (float*)d_out;
    int T = in_sizes[0] / HDIM;  // 16384

    cudaFuncSetAttribute(moe_gemm1, cudaFuncAttributeMaxDynamicSharedMemorySize, SMEM_BYTES);
    cudaFuncSetAttribute(moe_gemm2, cudaFuncAttributeMaxDynamicSharedMemorySize, SMEM_BYTES);

    zero_kernel<<<1024, 256>>>(out, (long long)out_size);
    router_kernel<<<(T + 7) / 8, 256>>>(x, Wg, T);
    scan_kernel<<<1, 32>>>();
    cvt_x_kernel<<<4096, 256>>>(x);
    tsplit_w_kernel<<<dim3(FDIM / 32, HDIM / 32, NE), dim3(32, 8)>>>(W1, 1);
    tsplit_w_kernel<<<dim3(HDIM / 32, FDIM / 32, NE), dim3(32, 8)>>>(W2, 2);
    moe_gemm1<<<dim3(FDIM / 128, MAXT / 128, NE), 128, SMEM_BYTES>>>();
    moe_gemm2<<<dim3(HDIM / 128, MAXT / 128, NE), 128, SMEM_BYTES>>>(out);
    finalize_kernel<<<1, 32>>>(out, (long long)out_size, T);
}

// round 10
// speedup vs baseline: 2.9152x; 1.1670x over previous
#include <cuda_runtime.h>
#include <cuda_fp16.h>
#include <math.h>
#include <stdint.h>

// Shapes fixed by dataset: x[8,2048,1024] f32, Wg[1024,8], W1[8,1024,2048],
// W2[8,2048,1024]. T = 16384 tokens, top-2 of 8 experts.
#define HDIM 1024
#define FDIM 2048
#define NE   8
#define MAXT 16384

// ------------------- device-global scratch ------------------------------
__device__ int   g_ecnt[NE];
__device__ int   g_off[NE + 1];
__device__ int   g_etok[NE * MAXT];
__device__ float g_ecw [NE * MAXT];
__device__ float g_zacc;
__device__ int   g_cnt0, g_cnt1;
__device__ float g_sumw0, g_sumw1;
// fp16 operands. Weights stored TRANSPOSED: w1t [e][F][H], w2t [e][H][F]
__device__ __half g_x [(size_t)MAXT * HDIM];
__device__ __half g_w1[(size_t)NE * HDIM * FDIM];
__device__ __half g_w2[(size_t)NE * FDIM * HDIM];
// hidden activations (compacted rows), K-contiguous [2T][F]
__device__ __half g_h [(size_t)2 * MAXT * FDIM];

// ------------------- helpers --------------------------------------------
__device__ __forceinline__ uint32_t smem_u32(const void* p) {
    uint32_t a;
    asm("{ .reg .u64 t; cvta.to.shared.u64 t, %1; cvt.u32.u64 %0, t; }"
        : "=r"(a) : "l"(p));
    return a;
}
__device__ __forceinline__ void cpa16(uint32_t dst, const void* src, bool valid) {
    int sz = valid ? 16 : 0;
    asm volatile("cp.async.cg.shared.global [%0], [%1], 16, %2;"
                 :: "r"(dst), "l"(src), "r"(sz) : "memory");
}
__device__ __forceinline__ void cpa_commit() {
    asm volatile("cp.async.commit_group;" ::: "memory");
}
__device__ __forceinline__ void mma_f16(float* c, const uint32_t* a, const uint32_t* b) {
    asm volatile(
        "mma.sync.aligned.m16n8k16.row.col.f32.f16.f16.f32 "
        "{%0,%1,%2,%3}, {%4,%5,%6,%7}, {%8,%9}, {%0,%1,%2,%3};"
        : "+f"(c[0]), "+f"(c[1]), "+f"(c[2]), "+f"(c[3])
        : "r"(a[0]), "r"(a[1]), "r"(a[2]), "r"(a[3]), "r"(b[0]), "r"(b[1]));
}
__device__ __forceinline__ void ldsm4(uint32_t addr, uint32_t* r) {
    asm volatile("ldmatrix.sync.aligned.m8n8.x4.shared.b16 {%0,%1,%2,%3}, [%4];"
                 : "=r"(r[0]), "=r"(r[1]), "=r"(r[2]), "=r"(r[3]) : "r"(addr));
}

// SMEM tile geometry: K-tile 32, rows 80 B (64 B payload + 16 pad).
// Banks 20r mod 32 distinct per 8-lane ldmatrix phase -> conflict-free.
#define ROWB 80
#define BSEG 10240           // 128 rows * 80 B
#define STAGEB 20480         // A | B
#define NSTAGE 3
#define SMEM_BYTES (NSTAGE * STAGEB)   // 61440

// ------------------- zero / reset ---------------------------------------
__global__ void zero_kernel(float* __restrict__ out, long long n) {
    long long i = (long long)blockIdx.x * blockDim.x + threadIdx.x;
    long long stride = (long long)gridDim.x * blockDim.x;
    for (; i < n; i += stride) out[i] = 0.0f;
    if (blockIdx.x == 0) {
        if (threadIdx.x == 0) {
            g_zacc = 0.0f; g_cnt0 = 0; g_cnt1 = 0;
            g_sumw0 = 0.0f; g_sumw1 = 0.0f;
        }
        if (threadIdx.x < NE) g_ecnt[threadIdx.x] = 0;
    }
}

// ------------------- router ---------------------------------------------
__global__ void router_kernel(const float* __restrict__ x,
                              const float* __restrict__ Wg, int T) {
    int warp = (blockIdx.x * blockDim.x + threadIdx.x) >> 5;
    int lane = threadIdx.x & 31;
    if (warp >= T) return;
    const float* xr = x + (size_t)warp * HDIM;

    float acc[NE];
#pragma unroll
    for (int e = 0; e < NE; ++e) acc[e] = 0.0f;
    for (int i = lane; i < HDIM; i += 32) {
        float xv = xr[i];
        float4 w0 = *(const float4*)(Wg + (size_t)i * NE);
        float4 w1 = *(const float4*)(Wg + (size_t)i * NE + 4);
        acc[0] += xv * w0.x; acc[1] += xv * w0.y;
        acc[2] += xv * w0.z; acc[3] += xv * w0.w;
        acc[4] += xv * w1.x; acc[5] += xv * w1.y;
        acc[6] += xv * w1.z; acc[7] += xv * w1.w;
    }
#pragma unroll
    for (int off = 16; off > 0; off >>= 1)
#pragma unroll
        for (int e = 0; e < NE; ++e)
            acc[e] += __shfl_xor_sync(0xFFFFFFFFu, acc[e], off);

    if (lane == 0) {
        float m = acc[0];
#pragma unroll
        for (int e = 1; e < NE; ++e) m = fmaxf(m, acc[e]);
        float p[NE], s = 0.0f;
#pragma unroll
        for (int e = 0; e < NE; ++e) { p[e] = __expf(acc[e] - m); s += p[e]; }
        float lse = m + logf(s);
        atomicAdd(&g_zacc, lse * lse);

        int i0 = 0;
#pragma unroll
        for (int e = 1; e < NE; ++e) if (p[e] > p[i0]) i0 = e;
        int i1 = (i0 == 0) ? 1 : 0;
#pragma unroll
        for (int e = 0; e < NE; ++e) if (e != i0 && p[e] > p[i1]) i1 = e;
        float w0 = p[i0] / s, w1 = p[i1] / s;

        atomicAdd(&g_sumw0, w0);
        atomicAdd(&g_sumw1, w1);
        if (i0 == 0 || i1 == 0) atomicAdd(&g_cnt0, 1);
        if (i0 == 1 || i1 == 1) atomicAdd(&g_cnt1, 1);

        int p0 = atomicAdd(&g_ecnt[i0], 1);
        g_etok[i0 * MAXT + p0] = warp; g_ecw[i0 * MAXT + p0] = w0;
        int p1 = atomicAdd(&g_ecnt[i1], 1);
        g_etok[i1 * MAXT + p1] = warp; g_ecw[i1 * MAXT + p1] = w1;
    }
}

__global__ void scan_kernel() {
    if (threadIdx.x == 0) {
        int s = 0; g_off[0] = 0;
        for (int e = 0; e < NE; ++e) { s += g_ecnt[e]; g_off[e + 1] = s; }
    }
}

// ------------------- x convert (linear, fp16) -----------------------------
__global__ void cvt_x_kernel(const float* __restrict__ src) {
    size_t n4 = (size_t)MAXT * HDIM / 4;
    for (size_t i = (size_t)blockIdx.x * blockDim.x + threadIdx.x; i < n4;
         i += (size_t)gridDim.x * blockDim.x) {
        float4 v = ((const float4*)src)[i];
        __half2* H = (__half2*)(g_x + i * 4);
        H[0] = __halves2half2(__float2half_rn(v.x), __float2half_rn(v.y));
        H[1] = __halves2half2(__float2half_rn(v.z), __float2half_rn(v.w));
    }
}

// ------------------- weight transpose (fp16) ------------------------------
// src [E][K][N] f32  ->  dst [E][N][K] fp16.  sel=1: W1, sel=2: W2.
__global__ void tsplit_w_kernel(const float* __restrict__ src, int sel) {
    int K = (sel == 1) ? HDIM : FDIM;
    int N = (sel == 1) ? FDIM : HDIM;
    __half* dst = (sel == 1) ? g_w1 : g_w2;
    __shared__ float t[32][33];
    int e = blockIdx.z;
    int k0 = blockIdx.y * 32, n0 = blockIdx.x * 32;
    const float* s = src + (size_t)e * K * N;
    __half* de = dst + (size_t)e * K * N;
    for (int i = threadIdx.y; i < 32; i += 8)
        t[i][threadIdx.x] = s[(size_t)(k0 + i) * N + n0 + threadIdx.x];
    __syncthreads();
    for (int i = threadIdx.y; i < 32; i += 8) {
        float v = t[threadIdx.x][i];
        de[(size_t)(n0 + i) * K + k0 + threadIdx.x] = __float2half_rn(v);
    }
}

// ========================================================================
// GEMM core: CTA 128x128, 8 warps (2M x 4N, warp tile 64x32), K-tile 32,
// mma.sync m16n8k16 fp16 single-term, 3-stage cp.async ring, 1 sync/iter.
// ========================================================================
__device__ __forceinline__ void load_tile32(
    uint32_t sb, int stage,
    const __half* a, bool av, long aoff,
    const __half* b, long boff,
    int tid, int kb)
{
    uint32_t buf = sb + stage * STAGEB;
    int row = tid >> 1;
    int hb  = (tid & 1) * 32;          // byte offset within 64B row payload
    int he  = (tid & 1) * 16;          // element offset
    uint32_t da = buf + row * ROWB + hb;
    uint32_t db = buf + BSEG + row * ROWB + hb;
    const __half* pa = a + aoff + kb + he;
    const __half* pb = b + boff + kb + he;
    cpa16(da,      pa,     av);
    cpa16(da + 16, pa + 8, av);
    cpa16(db,      pb,     true);
    cpa16(db + 16, pb + 8, true);
}

__device__ __forceinline__ void compute_stage32(
    uint32_t sb, int stage, int moff, int noff, int lane,
    float acc[4][4][4])
{
    uint32_t base = sb + stage * STAGEB;
    // A fragment: m0=(r0-7,k0-7) m1=(r8-15,k0-7) m2=(r0-7,k8-15) m3=(r8-15,k8-15)
    int arow = lane & 15;
    int akh  = (lane >> 4) << 4;                    // byte offset 0 / 16
    // B fragment: m0=(n0-7,k0-7) m1=(n0-7,k8-15) m2=(n8-15,k0-7) m3=(n8-15,k8-15)
    int brow = ((lane >> 4) & 1) * 8 + (lane & 7);
    int bkh  = ((lane >> 3) & 1) << 4;              // byte offset 0 / 16
#pragma unroll
    for (int ks = 0; ks < 2; ++ks) {
        int kby = ks * 32;
        uint32_t fa[4][4];
#pragma unroll
        for (int i = 0; i < 4; ++i) {
            uint32_t ra = base + (uint32_t)((moff + i * 16 + arow) * ROWB) +
                          kby + akh;
            ldsm4(ra, fa[i]);
        }
        uint32_t bb[2][4];
#pragma unroll
        for (int p = 0; p < 2; ++p) {
            uint32_t rb = base + BSEG +
                          (uint32_t)((noff + p * 16 + brow) * ROWB) + kby + bkh;
            ldsm4(rb, bb[p]);
        }
#pragma unroll
        for (int i = 0; i < 4; ++i)
#pragma unroll
            for (int j = 0; j < 4; ++j) {
                uint32_t* bj = &bb[j >> 1][(j & 1) * 2];
                mma_f16(acc[i][j], fa[i], bj);
            }
    }
}

// ------------------- GEMM1: h = gelu(gather(x) @ W1[e]) ------------------
__global__ __launch_bounds__(256, 2) void moe_gemm1() {
    int e = blockIdx.z;
    int n = g_ecnt[e];
    int row0 = blockIdx.y << 7;
    if (row0 >= n) return;
    int col0 = blockIdx.x << 7;

    extern __shared__ __align__(16) char smem[];
    uint32_t sb = smem_u32(smem);
    int tid = threadIdx.x, wid = tid >> 5, lane = tid & 31;
    int moff = (wid >> 2) * 64, noff = (wid & 3) * 32;

    const int* etok = g_etok + e * MAXT;
    int arow_g = row0 + (tid >> 1);
    bool av = arow_g < n;
    long aoff = av ? (long)etok[arow_g] * HDIM : 0;
    long boff = (long)(col0 + (tid >> 1)) * HDIM;
    const __half* W = g_w1 + (size_t)e * HDIM * FDIM;

    float acc[4][4][4];
#pragma unroll
    for (int i = 0; i < 4; ++i)
#pragma unroll
        for (int j = 0; j < 4; ++j)
#pragma unroll
            for (int q = 0; q < 4; ++q) acc[i][j][q] = 0.0f;

    const int KT = HDIM / 32;  // 32
    load_tile32(sb, 0, g_x, av, aoff, W, boff, tid, 0);
    cpa_commit();
    load_tile32(sb, 1, g_x, av, aoff, W, boff, tid, 32);
    cpa_commit();
    for (int kt = 0; kt < KT; ++kt) {
        asm volatile("cp.async.wait_group 1;" ::: "memory");
        __syncthreads();
        if (kt + 2 < KT)
            load_tile32(sb, (kt + 2) % NSTAGE, g_x, av, aoff, W, boff,
                        tid, (kt + 2) * 32);
        cpa_commit();
        compute_stage32(sb, kt % NSTAGE, moff, noff, lane, acc);
    }

    // epilogue: gelu -> fp16 h
    int lane4 = lane >> 2, lanec = (lane & 3) * 2;
    int hbase = g_off[e];
#pragma unroll
    for (int i = 0; i < 4; ++i) {
#pragma unroll
        for (int rr = 0; rr < 2; ++rr) {
            int r = row0 + moff + i * 16 + lane4 + rr * 8;
            if (r < n) {
                size_t base = (size_t)(hbase + r) * FDIM + col0 + noff;
#pragma unroll
                for (int j = 0; j < 4; ++j) {
                    float vA = acc[i][j][rr * 2 + 0];
                    float vB = acc[i][j][rr * 2 + 1];
                    float gA = 0.5f * vA * (1.0f + erff(vA * 0.70710678118654752f));
                    float gB = 0.5f * vB * (1.0f + erff(vB * 0.70710678118654752f));
                    *(__half2*)(g_h + base + j * 8 + lanec) =
                        __halves2half2(__float2half_rn(gA), __float2half_rn(gB));
                }
            }
        }
    }
}

// ------------------- GEMM2: out += cw * (h @ W2[e]) ----------------------
__global__ __launch_bounds__(256, 2) void moe_gemm2(float* __restrict__ out) {
    int e = blockIdx.z;
    int n = g_ecnt[e];
    int row0 = blockIdx.y << 7;
    if (row0 >= n) return;
    int col0 = blockIdx.x << 7;

    extern __shared__ __align__(16) char smem[];
    uint32_t sb = smem_u32(smem);
    int tid = threadIdx.x, wid = tid >> 5, lane = tid & 31;
    int moff = (wid >> 2) * 64, noff = (wid & 3) * 32;

    int hbase = g_off[e];
    int arow_g = row0 + (tid >> 1);
    bool av = arow_g < n;
    long aoff = (long)(hbase + arow_g) * FDIM;
    long boff = (long)(col0 + (tid >> 1)) * FDIM;
    const __half* W = g_w2 + (size_t)e * FDIM * HDIM;

    float acc[4][4][4];
#pragma unroll
    for (int i = 0; i < 4; ++i)
#pragma unroll
        for (int j = 0; j < 4; ++j)
#pragma unroll
            for (int q = 0; q < 4; ++q) acc[i][j][q] = 0.0f;

    const int KT = FDIM / 32;  // 64
    load_tile32(sb, 0, g_h, av, aoff, W, boff, tid, 0);
    cpa_commit();
    load_tile32(sb, 1, g_h, av, aoff, W, boff, tid, 32);
    cpa_commit();
    for (int kt = 0; kt < KT; ++kt) {
        asm volatile("cp.async.wait_group 1;" ::: "memory");
        __syncthreads();
        if (kt + 2 < KT)
            load_tile32(sb, (kt + 2) % NSTAGE, g_h, av, aoff, W, boff,
                        tid, (kt + 2) * 32);
        cpa_commit();
        compute_stage32(sb, kt % NSTAGE, moff, noff, lane, acc);
    }

    // epilogue: weighted atomic scatter into out
    int lane4 = lane >> 2, lanec = (lane & 3) * 2;
#pragma unroll
    for (int i = 0; i < 4; ++i) {
#pragma unroll
        for (int rr = 0; rr < 2; ++rr) {
            int r = row0 + moff + i * 16 + lane4 + rr * 8;
            if (r < n) {
                int   t = g_etok[e * MAXT + r];
                float w = g_ecw [e * MAXT + r];
                float* orow = out + (size_t)t * HDIM + col0 + noff;
#pragma unroll
                for (int j = 0; j < 4; ++j) {
                    atomicAdd(&orow[j * 8 + lanec],     w * acc[i][j][rr * 2 + 0]);
                    atomicAdd(&orow[j * 8 + lanec + 1], w * acc[i][j][rr * 2 + 1]);
                }
            }
        }
    }
}

// ------------------- losses ---------------------------------------------
__global__ void finalize_kernel(float* __restrict__ out, long long out_size, int T) {
    if (blockIdx.x == 0 && threadIdx.x == 0) {
        long long base = (long long)T * HDIM;
        float invT = 1.0f / (float)T;
        float z = g_zacc * invT;
        float tpe0 = (float)g_cnt0 * invT, tpe1 = (float)g_cnt1 * invT;
        float rpp0 = g_sumw0 * invT,       rpp1 = g_sumw1 * invT;
        float aux = 2.0f * (tpe0 * rpp0 + tpe1 * rpp1);
        if (base < out_size)     out[base]     = z;
        if (base + 1 < out_size) out[base + 1] = aux;
    }
}

// ------------------- launch ---------------------------------------------
extern "C" void kernel_launch(void* const* d_in, const int* in_sizes, int n_in,
                              void* d_out, int out_size) {
    const float* x  = (const float*)d_in[0];
    const float* Wg = (const float*)d_in[1];
    const float* W1 = (const float*)d_in[2];
    const float* W2 = (const float*)d_in[3];
    float* out = (float*)d_out;
    int T = in_sizes[0] / HDIM;  // 16384

    cudaFuncSetAttribute(moe_gemm1, cudaFuncAttributeMaxDynamicSharedMemorySize, SMEM_BYTES);
    cudaFuncSetAttribute(moe_gemm2, cudaFuncAttributeMaxDynamicSharedMemorySize, SMEM_BYTES);

    zero_kernel<<<1024, 256>>>(out, (long long)out_size);
    router_kernel<<<(T + 7) / 8, 256>>>(x, Wg, T);
    scan_kernel<<<1, 32>>>();
    cvt_x_kernel<<<4096, 256>>>(x);
    tsplit_w_kernel<<<dim3(FDIM / 32, HDIM / 32, NE), dim3(32, 8)>>>(W1, 1);
    tsplit_w_kernel<<<dim3(HDIM / 32, FDIM / 32, NE), dim3(32, 8)>>>(W2, 2);
    moe_gemm1<<<dim3(FDIM / 128, MAXT / 128, NE), 256, SMEM_BYTES>>>();
    moe_gemm2<<<dim3(HDIM / 128, MAXT / 128, NE), 256, SMEM_BYTES>>>(out);
    finalize_kernel<<<1, 32>>>(out, (long long)out_size, T);
}